// round 15
// baseline (speedup 1.0000x reference)
#include <cuda_runtime.h>
#include <cuda_fp16.h>
#include <stdint.h>

#define BB 16
#define PP 8192
#define MM 128
#define KNN 16
#define DD 768
#define QQ (BB*MM)      // 2048 queries/tokens
#define RR (QQ*KNN)     // 32768 gathered rows

// ---------------- scratch (device globals; no allocation allowed) ----------------
__device__ float  g_cent[QQ*4];
__device__ int    g_knn[RR];
__device__ int    g_prog[BB];
__device__ __half g_bufA[(size_t)RR*768];
__device__ __half g_bufB[(size_t)RR*768];
__device__ __half g_pool[(size_t)QQ*DD];
__device__ __half g_h[(size_t)QQ*DD];
// transposed weights [N][K] (K-major so B operand is k-contiguous = "col" for mma)
#define OFF_W2T  0
#define OFF_W3T  (512*256)
#define OFF_W4T  (OFF_W3T + 768*512)
#define OFF_WA1T (OFF_W4T + 768*768)
#define OFF_WA2T (OFF_WA1T + 768*768)
__device__ __half g_wt[OFF_WA2T + 768*768];

// transpose ranges (element counts)
#define TN_W2  (256*512)
#define TN_W3  (512*768)
#define TN_W44 (768*768)
#define TE1 TN_W2
#define TE2 (TE1 + TN_W3)
#define TE3 (TE2 + TN_W44)
#define TE4 (TE3 + TN_W44)
#define TE5 (TE4 + TN_W44)
#define TE6 (TE5 + QQ)
#define NT_BLK ((TE6 + 1023) / 1024)        // transpose blocks (1024 thr each)
#define FUSED_GRID (BB + NT_BLK + QQ)       // fps + transpose + knn blocks

// ---------------- reset progress flags (runs before fused kernel each replay) -----
__global__ void reset_prog()
{
    if (threadIdx.x < BB) g_prog[threadIdx.x] = 0;
}

// ================= fused FPS + transpose + kNN ====================================
__global__ __launch_bounds__(1024) void fused_front(
    const float* __restrict__ coords,
    float* __restrict__ cent_out2,
    const float* __restrict__ W2, const float* __restrict__ W3,
    const float* __restrict__ W4, const float* __restrict__ Wa1,
    const float* __restrict__ Wa2, float* __restrict__ masks)
{
    int bid = blockIdx.x;
    int tid = threadIdx.x;

    if (bid < BB) {
        // ---------------- FPS ----------------
        int b = bid;
        float px[8], py[8], pz[8], pw[8], dmin[8];
#pragma unroll
        for (int i = 0; i < 8; i++) {
            int p = tid + i * 1024;
            const float* c = coords + ((size_t)b * PP + p) * 5;
            px[i] = c[1]; py[i] = c[2]; pz[i] = c[3]; pw[i] = c[4];
            dmin[i] = 1e30f;
        }
        __shared__ float last[4];
        __shared__ unsigned long long red[32];
        __shared__ int cur_s;
        int cur = 0;
        for (int m = 0; m < MM; m++) {
            if (tid == (cur & 1023)) {
                int i = cur >> 10;
                last[0] = px[i]; last[1] = py[i]; last[2] = pz[i]; last[3] = pw[i];
                float* o  = g_cent + ((size_t)b * MM + m) * 4;
                o[0] = px[i]; o[1] = py[i]; o[2] = pz[i]; o[3] = pw[i];
                float* o2 = cent_out2 + ((size_t)b * MM + m) * 4;
                o2[0] = px[i]; o2[1] = py[i]; o2[2] = pz[i]; o2[3] = pw[i];
                __threadfence();
                ((volatile int*)g_prog)[b] = m + 1;      // release centroid m
            }
            __syncthreads();
            if (m == MM - 1) break;
            float lx = last[0], ly = last[1], lz = last[2], lw = last[3];
            float bestv = -1.0f;
            int   besti = 0;
#pragma unroll
            for (int i = 0; i < 8; i++) {
                float dx = __fsub_rn(px[i], lx);
                float dy = __fsub_rn(py[i], ly);
                float dz = __fsub_rn(pz[i], lz);
                float dw = __fsub_rn(pw[i], lw);
                float d = __fadd_rn(__fadd_rn(__fadd_rn(__fmul_rn(dx,dx), __fmul_rn(dy,dy)),
                                              __fmul_rn(dz,dz)), __fmul_rn(dw,dw));
                float dm = fminf(dmin[i], d);
                dmin[i] = dm;
                if (dm > bestv) { bestv = dm; besti = tid + i * 1024; }
            }
            unsigned long long best = ((unsigned long long)__float_as_uint(bestv) << 32)
                                    | (unsigned)(0x7FFFFFFF - besti);
            for (int off = 16; off; off >>= 1) {
                unsigned long long o = __shfl_down_sync(0xFFFFFFFFu, best, off);
                if (o > best) best = o;
            }
            if ((tid & 31) == 0) red[tid >> 5] = best;
            __syncthreads();
            if (tid < 32) {
                unsigned long long v = red[tid];
                for (int off = 16; off; off >>= 1) {
                    unsigned long long o = __shfl_down_sync(0xFFFFFFFFu, v, off);
                    if (o > v) v = o;
                }
                if (tid == 0) cur_s = 0x7FFFFFFF - (int)(v & 0xFFFFFFFFu);
            }
            __syncthreads();
            cur = cur_s;
        }
        return;
    }

    if (bid < BB + NT_BLK) {
        // ---------------- weight transpose + mask fill ----------------
        int i = (bid - BB) * 1024 + tid;
        const float* W; __half* dst; int N, K, j;
        if (i < TE1)      { j = i;       W = W2;  dst = g_wt + OFF_W2T;  K = 256; N = 512; }
        else if (i < TE2) { j = i - TE1; W = W3;  dst = g_wt + OFF_W3T;  K = 512; N = 768; }
        else if (i < TE3) { j = i - TE2; W = W4;  dst = g_wt + OFF_W4T;  K = 768; N = 768; }
        else if (i < TE4) { j = i - TE3; W = Wa1; dst = g_wt + OFF_WA1T; K = 768; N = 768; }
        else if (i < TE5) { j = i - TE4; W = Wa2; dst = g_wt + OFF_WA2T; K = 768; N = 768; }
        else if (i < TE6) { masks[i - TE5] = 1.0f; return; }
        else return;
        int k = j / N, n = j % N;
        dst[(size_t)n * K + k] = __float2half_rn(W[j]);
        return;
    }

    // ---------------- kNN (1024 threads, 8 pts/thread) ----------------
    {
        extern __shared__ unsigned long long keys[];   // PP entries
        __shared__ unsigned long long red2[32];
        __shared__ unsigned long long win_s;
        int lin = bid - BB - NT_BLK;
        int m = lin >> 4;          // slow: early blocks need early centroids
        int b = lin & 15;

        if (tid == 0) {
            while (((volatile int*)g_prog)[b] <= m) __nanosleep(100);
            __threadfence();       // acquire
        }
        __syncthreads();

        const float* c = g_cent + ((size_t)b * MM + m) * 4;
        float c0 = __ldcg(c + 0), c1 = __ldcg(c + 1), c2 = __ldcg(c + 2), c3 = __ldcg(c + 3);
        float cen2 = __fadd_rn(__fadd_rn(__fadd_rn(__fmul_rn(c0,c0), __fmul_rn(c1,c1)),
                                         __fmul_rn(c2,c2)), __fmul_rn(c3,c3));
        unsigned long long mymin = ~0ull;
#pragma unroll
        for (int it = 0; it < PP / 1024; it++) {
            int p = tid + it * 1024;
            const float* q = coords + ((size_t)b * PP + p) * 5;
            float x0 = q[1], x1 = q[2], x2 = q[3], x3 = q[4];
            float pts2 = __fadd_rn(__fadd_rn(__fadd_rn(__fmul_rn(x0,x0), __fmul_rn(x1,x1)),
                                             __fmul_rn(x2,x2)), __fmul_rn(x3,x3));
            float dot  = __fadd_rn(__fadd_rn(__fadd_rn(__fmul_rn(c0,x0), __fmul_rn(c1,x1)),
                                             __fmul_rn(c2,x2)), __fmul_rn(c3,x3));
            float d2 = __fsub_rn(__fadd_rn(cen2, pts2), __fmul_rn(2.0f, dot));
            unsigned u = __float_as_uint(d2);
            u = (u & 0x80000000u) ? ~u : (u | 0x80000000u);   // order-preserving map
            unsigned long long key = ((unsigned long long)u << 32) | (unsigned)p;
            keys[p] = key;
            if (key < mymin) mymin = key;
        }
        __syncthreads();

        int* outp = g_knn + ((size_t)b * MM + m) * KNN;
        for (int k = 0; k < KNN; k++) {
            unsigned long long v = mymin;
            for (int off = 16; off; off >>= 1) {
                unsigned long long o = __shfl_down_sync(0xFFFFFFFFu, v, off);
                if (o < v) v = o;
            }
            if ((tid & 31) == 0) red2[tid >> 5] = v;
            __syncthreads();
            if (tid < 32) {
                unsigned long long w = red2[tid];
                for (int off = 16; off; off >>= 1) {
                    unsigned long long o = __shfl_down_sync(0xFFFFFFFFu, w, off);
                    if (o < w) w = o;
                }
                if (tid == 0) {
                    win_s = w;
                    outp[k] = (int)(w & 0xFFFFFFFFu);
                }
            }
            __syncthreads();
            if (mymin == win_s) {
                keys[(unsigned)(mymin & 0xFFFFFFFFu)] = ~0ull;
                unsigned long long nm = ~0ull;
#pragma unroll
                for (int it = 0; it < PP / 1024; it++) {
                    unsigned long long t = keys[tid + it * 1024];
                    if (t < nm) nm = t;
                }
                mymin = nm;
            }
        }
    }
}

// ---------------- gather + layer1 (6 -> 256, relu): 8 rows per block, fp16 out ----
__global__ __launch_bounds__(256) void gather_mlp1(const float* __restrict__ feats,
                                                   const float* __restrict__ W1,
                                                   const float* __restrict__ b1)
{
    int j = threadIdx.x;
    int rowbase = blockIdx.x * 8;
    float w[6];
#pragma unroll
    for (int t = 0; t < 6; t++) w[t] = W1[t * 256 + j];
    float bb = b1[j];
    __shared__ float fs[8][6];
    if (j < 48) {
        int r = j / 6, cidx = j % 6;
        int row = rowbase + r;
        int bidx = row >> 11;                       // row / (MM*KNN)
        int idx = g_knn[row];
        fs[r][cidx] = feats[((size_t)bidx * PP + idx) * 6 + cidx];
    }
    __syncthreads();
#pragma unroll
    for (int r = 0; r < 8; r++) {
        float acc = bb;
#pragma unroll
        for (int t = 0; t < 6; t++) acc = fmaf(fs[r][t], w[t], acc);
        g_bufA[(size_t)(rowbase + r) * 256 + j] = __float2half_rn(fmaxf(acc, 0.f));
    }
}

// ================= fp16 mma.sync m16n8k16 GEMM, 512 threads (16 warps) =============
// C[Mr,N] = act(A[Mr,K] @ Bt[N,K]^T + bias)    (A, Bt fp16; accumulate fp32)
// CTA tile 128x128, K chunks of 64 halves, 3-stage cp.async.
// 16 warps: 4(m) x 4(n); warp tile 32x32 -> 2 mt x 4 nt fragments, acc = 32 regs.
#define SPAD 36                      // smem row stride in 32-bit words (=72 halves)
#define STG_MAT (128 * SPAD * 4)     // 18432 B per matrix per stage
#define STG_BYTES (2 * STG_MAT)      // 36864 B per stage (A + B)
#define NSTAGE 3
#define GSMEM (NSTAGE * STG_BYTES)   // 110592 B

__device__ __forceinline__ void cp16(uint32_t saddr, const void* g) {
    asm volatile("cp.async.cg.shared.global [%0], [%1], 16;" :: "r"(saddr), "l"(g));
}
__device__ __forceinline__ void ldmx4(uint32_t& r0, uint32_t& r1, uint32_t& r2, uint32_t& r3,
                                      uint32_t saddr) {
    asm volatile("ldmatrix.sync.aligned.m8n8.x4.shared.b16 {%0,%1,%2,%3}, [%4];"
                 : "=r"(r0), "=r"(r1), "=r"(r2), "=r"(r3) : "r"(saddr));
}

template<bool RELU, bool POOL, bool HALF_OUT>
__global__ __launch_bounds__(512, 2) void mma_gemm(
    const __half* __restrict__ A, const __half* __restrict__ Bt,
    const float* __restrict__ bias, void* __restrict__ Cv,
    int N, int K)
{
    extern __shared__ char dsm[];
    uint32_t sbase = (uint32_t)__cvta_generic_to_shared(dsm);
    int tid = threadIdx.x, wid = tid >> 5, lane = tid & 31;
    int gid = lane >> 2, tig = lane & 3;
    int bx = blockIdx.x, by = blockIdx.y;
    int m_base = (wid & 3) * 32;
    int n_base = (wid >> 2) * 32;

    const __half* Ag = A  + (size_t)(by * 128) * K;
    const __half* Bg = Bt + (size_t)(bx * 128) * K;

    // staging: 1024 16B-units per matrix per chunk; 512 threads -> 2 units each
    int srow0 = tid >> 3,          sq0 = tid & 7;
    int srow1 = (tid + 512) >> 3,  sq1 = tid & 7;   // (tid+512)&7 == tid&7

    // ldmatrix per-thread word offsets
    int lr = lane & 7, mi = lane >> 3;
    int a_off[2], b_off[2];
#pragma unroll
    for (int mt = 0; mt < 2; mt++)
        a_off[mt] = (m_base + mt * 16 + lr + (mi & 1) * 8) * SPAD + (mi >> 1) * 4;
#pragma unroll
    for (int nt2 = 0; nt2 < 2; nt2++)
        b_off[nt2] = (n_base + nt2 * 16 + lr + (mi >> 1) * 8) * SPAD + (mi & 1) * 4;

    float acc[2][4][4];
#pragma unroll
    for (int mt = 0; mt < 2; mt++)
#pragma unroll
        for (int nt = 0; nt < 4; nt++)
#pragma unroll
            for (int j = 0; j < 4; j++) acc[mt][nt][j] = 0.f;

    int NC = K >> 6;   // chunks of 64 halves

#pragma unroll
    for (int s = 0; s < 2; s++) {
        int kb = s << 6;
        uint32_t stb = sbase + s * STG_BYTES;
        uint32_t d0 = (uint32_t)(srow0 * (SPAD * 4) + sq0 * 16);
        uint32_t d1 = (uint32_t)(srow1 * (SPAD * 4) + sq1 * 16);
        cp16(stb + d0,           Ag + (size_t)srow0 * K + kb + sq0 * 8);
        cp16(stb + d1,           Ag + (size_t)srow1 * K + kb + sq1 * 8);
        cp16(stb + STG_MAT + d0, Bg + (size_t)srow0 * K + kb + sq0 * 8);
        cp16(stb + STG_MAT + d1, Bg + (size_t)srow1 * K + kb + sq1 * 8);
        asm volatile("cp.async.commit_group;" ::: "memory");
    }

    for (int c = 0; c < NC; c++) {
        asm volatile("cp.async.wait_group 1;" ::: "memory");
        __syncthreads();

        if (c + 2 < NC) {
            int kb = (c + 2) << 6;
            uint32_t stb = sbase + ((c + 2) % NSTAGE) * STG_BYTES;
            uint32_t d0 = (uint32_t)(srow0 * (SPAD * 4) + sq0 * 16);
            uint32_t d1 = (uint32_t)(srow1 * (SPAD * 4) + sq1 * 16);
            cp16(stb + d0,           Ag + (size_t)srow0 * K + kb + sq0 * 8);
            cp16(stb + d1,           Ag + (size_t)srow1 * K + kb + sq1 * 8);
            cp16(stb + STG_MAT + d0, Bg + (size_t)srow0 * K + kb + sq0 * 8);
            cp16(stb + STG_MAT + d1, Bg + (size_t)srow1 * K + kb + sq1 * 8);
        }
        asm volatile("cp.async.commit_group;" ::: "memory");

        uint32_t aBase = sbase + (c % NSTAGE) * STG_BYTES;
        uint32_t bBase = aBase + STG_MAT;

#pragma unroll
        for (int ks = 0; ks < 4; ks++) {
            int k0 = ks * 8;
            uint32_t af[2][4];
#pragma unroll
            for (int mt = 0; mt < 2; mt++)
                ldmx4(af[mt][0], af[mt][1], af[mt][2], af[mt][3],
                      aBase + (uint32_t)(a_off[mt] + k0) * 4);
#pragma unroll
            for (int nt2 = 0; nt2 < 2; nt2++) {
                uint32_t bf0, bf1, bf2, bf3;
                ldmx4(bf0, bf1, bf2, bf3, bBase + (uint32_t)(b_off[nt2] + k0) * 4);
#pragma unroll
                for (int mt = 0; mt < 2; mt++) {
                    asm volatile(
                        "mma.sync.aligned.m16n8k16.row.col.f32.f16.f16.f32 "
                        "{%0,%1,%2,%3}, {%4,%5,%6,%7}, {%8,%9}, {%0,%1,%2,%3};"
                        : "+f"(acc[mt][nt2*2][0]), "+f"(acc[mt][nt2*2][1]),
                          "+f"(acc[mt][nt2*2][2]), "+f"(acc[mt][nt2*2][3])
                        : "r"(af[mt][0]), "r"(af[mt][1]), "r"(af[mt][2]), "r"(af[mt][3]),
                          "r"(bf0), "r"(bf1));
                }
#pragma unroll
                for (int mt = 0; mt < 2; mt++) {
                    asm volatile(
                        "mma.sync.aligned.m16n8k16.row.col.f32.f16.f16.f32 "
                        "{%0,%1,%2,%3}, {%4,%5,%6,%7}, {%8,%9}, {%0,%1,%2,%3};"
                        : "+f"(acc[mt][nt2*2+1][0]), "+f"(acc[mt][nt2*2+1][1]),
                          "+f"(acc[mt][nt2*2+1][2]), "+f"(acc[mt][nt2*2+1][3])
                        : "r"(af[mt][0]), "r"(af[mt][1]), "r"(af[mt][2]), "r"(af[mt][3]),
                          "r"(bf2), "r"(bf3));
                }
            }
        }
    }

    // ---- epilogue (fragment ownership convention unchanged) ----
#pragma unroll
    for (int nt = 0; nt < 4; nt++) {
        int cg = bx * 128 + n_base + nt * 8 + 2 * tig;
        float bz0 = bias[cg], bz1 = bias[cg + 1];
#pragma unroll
        for (int mt = 0; mt < 2; mt++) {
            float v0 = acc[mt][nt][0] + bz0;
            float v1 = acc[mt][nt][1] + bz1;
            float v2 = acc[mt][nt][2] + bz0;
            float v3 = acc[mt][nt][3] + bz1;
            if (RELU) {
                v0 = fmaxf(v0, 0.f); v1 = fmaxf(v1, 0.f);
                v2 = fmaxf(v2, 0.f); v3 = fmaxf(v3, 0.f);
            }
            if (POOL) {
                float m0 = fmaxf(v0, v2);
                float m1 = fmaxf(v1, v3);
#pragma unroll
                for (int off = 4; off <= 16; off <<= 1) {
                    m0 = fmaxf(m0, __shfl_xor_sync(0xFFFFFFFFu, m0, off));
                    m1 = fmaxf(m1, __shfl_xor_sync(0xFFFFFFFFu, m1, off));
                }
                if (gid == 0) {
                    int q = (by * 128 + m_base + mt * 16) >> 4;
                    __half* C = (__half*)Cv;
                    *(__half2*)(C + (size_t)q * N + cg) = __floats2half2_rn(m0, m1);
                }
            } else if (HALF_OUT) {
                int rg = by * 128 + m_base + mt * 16 + gid;
                __half* C = (__half*)Cv;
                *(__half2*)(C + (size_t)rg * N + cg)       = __floats2half2_rn(v0, v1);
                *(__half2*)(C + (size_t)(rg + 8) * N + cg) = __floats2half2_rn(v2, v3);
            } else {
                int rg = by * 128 + m_base + mt * 16 + gid;
                float* C = (float*)Cv;
                *(float2*)(C + (size_t)rg * N + cg)       = make_float2(v0, v1);
                *(float2*)(C + (size_t)(rg + 8) * N + cg) = make_float2(v2, v3);
            }
        }
    }
}

// ---------------- launcher ---------------------------------------------------------
extern "C" void kernel_launch(void* const* d_in, const int* in_sizes, int n_in,
                              void* d_out, int out_size)
{
    const float* coords = (const float*)d_in[0];
    const float* feats  = (const float*)d_in[1];
    const float* W1 = (const float*)d_in[2];  const float* b1 = (const float*)d_in[3];
    const float* W2 = (const float*)d_in[4];  const float* b2 = (const float*)d_in[5];
    const float* W3 = (const float*)d_in[6];  const float* b3 = (const float*)d_in[7];
    const float* W4 = (const float*)d_in[8];  const float* b4 = (const float*)d_in[9];
    const float* Wa1 = (const float*)d_in[10]; const float* ba1 = (const float*)d_in[11];
    const float* Wa2 = (const float*)d_in[12]; const float* ba2 = (const float*)d_in[13];

    float* out     = (float*)d_out;
    float* tokens  = out;                               // [QQ, DD]
    float* centout = out + (size_t)QQ * DD;             // [QQ, 4]
    float* masks   = centout + (size_t)QQ * 4;          // [QQ]

    __half *pA, *pB, *pPool, *pH, *pWt;
    cudaGetSymbolAddress((void**)&pA, g_bufA);
    cudaGetSymbolAddress((void**)&pB, g_bufB);
    cudaGetSymbolAddress((void**)&pPool, g_pool);
    cudaGetSymbolAddress((void**)&pH, g_h);
    cudaGetSymbolAddress((void**)&pWt, g_wt);

    // 1. reset centroid-progress flags (must precede fused kernel every replay)
    reset_prog<<<1, 32>>>();

    // 2. fused FPS + transpose/mask + kNN (kNN overlaps FPS via progress flags)
    cudaFuncSetAttribute(fused_front, cudaFuncAttributeMaxDynamicSharedMemorySize, PP * 8);
    fused_front<<<FUSED_GRID, 1024, PP * 8>>>(coords, centout,
                                              W2, W3, W4, Wa1, Wa2, masks);

    // 3. gather + layer1 (6 -> 256, relu, fp16 out) -> g_bufA
    gather_mlp1<<<RR / 8, 256>>>(feats, W1, b1);

    // 4. MLP chain on fp16 tensor cores (512-thread CTAs); layer 4 fuses max-pool
    cudaFuncSetAttribute((const void*)mma_gemm<true,  false, true >, cudaFuncAttributeMaxDynamicSharedMemorySize, GSMEM);
    cudaFuncSetAttribute((const void*)mma_gemm<false, true,  true >, cudaFuncAttributeMaxDynamicSharedMemorySize, GSMEM);
    cudaFuncSetAttribute((const void*)mma_gemm<false, false, false>, cudaFuncAttributeMaxDynamicSharedMemorySize, GSMEM);
    mma_gemm<true,  false, true ><<<dim3(512 / 128, RR / 128), 512, GSMEM>>>(pA, pWt + OFF_W2T, b2, pB, 512, 256);
    mma_gemm<true,  false, true ><<<dim3(768 / 128, RR / 128), 512, GSMEM>>>(pB, pWt + OFF_W3T, b3, pA, 768, 512);
    // layer 4: output pooled directly into g_pool [QQ, 768] (fp16)
    mma_gemm<false, true,  true ><<<dim3(768 / 128, RR / 128), 512, GSMEM>>>(pA, pWt + OFF_W4T, b4, pPool, 768, 768);

    // 5. attention MLP -> tokens (final layer fp32 out)
    mma_gemm<true,  false, true ><<<dim3(DD / 128, QQ / 128), 512, GSMEM>>>(pPool, pWt + OFF_WA1T, ba1, pH, 768, 768);
    mma_gemm<false, false, false><<<dim3(DD / 128, QQ / 128), 512, GSMEM>>>(pH, pWt + OFF_WA2T, ba2, tokens, 768, 768);
}

// round 16
// speedup vs baseline: 1.0211x; 1.0211x over previous
#include <cuda_runtime.h>
#include <cuda_fp16.h>
#include <stdint.h>

#define BB 16
#define PP 8192
#define MM 128
#define KNN 16
#define DD 768
#define QQ (BB*MM)      // 2048 queries/tokens
#define RR (QQ*KNN)     // 32768 gathered rows

// ---------------- scratch (device globals; no allocation allowed) ----------------
__device__ float  g_cent[QQ*4];
__device__ int    g_knn[RR];
__device__ int    g_prog[BB];
__device__ __half g_bufA[(size_t)RR*768];
__device__ __half g_bufB[(size_t)RR*768];
__device__ __half g_pool[(size_t)QQ*DD];
__device__ __half g_h[(size_t)QQ*DD];
// transposed weights [N][K] (K-major so B operand is k-contiguous = "col" for mma)
#define OFF_W2T  0
#define OFF_W3T  (512*256)
#define OFF_W4T  (OFF_W3T + 768*512)
#define OFF_WA1T (OFF_W4T + 768*768)
#define OFF_WA2T (OFF_WA1T + 768*768)
__device__ __half g_wt[OFF_WA2T + 768*768];

// transpose ranges (element counts)
#define TN_W2  (256*512)
#define TN_W3  (512*768)
#define TN_W44 (768*768)
#define TE1 TN_W2
#define TE2 (TE1 + TN_W3)
#define TE3 (TE2 + TN_W44)
#define TE4 (TE3 + TN_W44)
#define TE5 (TE4 + TN_W44)
#define TE6 (TE5 + QQ)
#define NT_BLK ((TE6 + 1023) / 1024)        // transpose blocks (1024 thr each)
#define FUSED_GRID (BB + NT_BLK + QQ)       // fps + transpose + knn blocks

// ---------------- reset progress flags (runs before fused kernel each replay) -----
__global__ void reset_prog()
{
    if (threadIdx.x < BB) g_prog[threadIdx.x] = 0;
}

// ================= fused FPS + transpose + kNN ====================================
__global__ __launch_bounds__(1024) void fused_front(
    const float* __restrict__ coords,
    float* __restrict__ cent_out2,
    const float* __restrict__ W2, const float* __restrict__ W3,
    const float* __restrict__ W4, const float* __restrict__ Wa1,
    const float* __restrict__ Wa2, float* __restrict__ masks)
{
    int bid = blockIdx.x;
    int tid = threadIdx.x;

    if (bid < BB) {
        // ---------------- FPS ----------------
        int b = bid;
        float px[8], py[8], pz[8], pw[8], dmin[8];
#pragma unroll
        for (int i = 0; i < 8; i++) {
            int p = tid + i * 1024;
            const float* c = coords + ((size_t)b * PP + p) * 5;
            px[i] = c[1]; py[i] = c[2]; pz[i] = c[3]; pw[i] = c[4];
            dmin[i] = 1e30f;
        }
        __shared__ float last[4];
        __shared__ unsigned long long red[32];
        __shared__ int cur_s;
        int cur = 0;
        for (int m = 0; m < MM; m++) {
            if (tid == (cur & 1023)) {
                int i = cur >> 10;
                last[0] = px[i]; last[1] = py[i]; last[2] = pz[i]; last[3] = pw[i];
                float* o  = g_cent + ((size_t)b * MM + m) * 4;
                o[0] = px[i]; o[1] = py[i]; o[2] = pz[i]; o[3] = pw[i];
                float* o2 = cent_out2 + ((size_t)b * MM + m) * 4;
                o2[0] = px[i]; o2[1] = py[i]; o2[2] = pz[i]; o2[3] = pw[i];
                __threadfence();
                ((volatile int*)g_prog)[b] = m + 1;      // release centroid m
            }
            __syncthreads();
            if (m == MM - 1) break;
            float lx = last[0], ly = last[1], lz = last[2], lw = last[3];
            float bestv = -1.0f;
            int   besti = 0;
#pragma unroll
            for (int i = 0; i < 8; i++) {
                float dx = __fsub_rn(px[i], lx);
                float dy = __fsub_rn(py[i], ly);
                float dz = __fsub_rn(pz[i], lz);
                float dw = __fsub_rn(pw[i], lw);
                float d = __fadd_rn(__fadd_rn(__fadd_rn(__fmul_rn(dx,dx), __fmul_rn(dy,dy)),
                                              __fmul_rn(dz,dz)), __fmul_rn(dw,dw));
                float dm = fminf(dmin[i], d);
                dmin[i] = dm;
                if (dm > bestv) { bestv = dm; besti = tid + i * 1024; }
            }
            unsigned long long best = ((unsigned long long)__float_as_uint(bestv) << 32)
                                    | (unsigned)(0x7FFFFFFF - besti);
            for (int off = 16; off; off >>= 1) {
                unsigned long long o = __shfl_down_sync(0xFFFFFFFFu, best, off);
                if (o > best) best = o;
            }
            if ((tid & 31) == 0) red[tid >> 5] = best;
            __syncthreads();
            if (tid < 32) {
                unsigned long long v = red[tid];
                for (int off = 16; off; off >>= 1) {
                    unsigned long long o = __shfl_down_sync(0xFFFFFFFFu, v, off);
                    if (o > v) v = o;
                }
                if (tid == 0) cur_s = 0x7FFFFFFF - (int)(v & 0xFFFFFFFFu);
            }
            __syncthreads();
            cur = cur_s;
        }
        return;
    }

    if (bid < BB + NT_BLK) {
        // ---------------- weight transpose + mask fill ----------------
        int i = (bid - BB) * 1024 + tid;
        const float* W; __half* dst; int N, K, j;
        if (i < TE1)      { j = i;       W = W2;  dst = g_wt + OFF_W2T;  K = 256; N = 512; }
        else if (i < TE2) { j = i - TE1; W = W3;  dst = g_wt + OFF_W3T;  K = 512; N = 768; }
        else if (i < TE3) { j = i - TE2; W = W4;  dst = g_wt + OFF_W4T;  K = 768; N = 768; }
        else if (i < TE4) { j = i - TE3; W = Wa1; dst = g_wt + OFF_WA1T; K = 768; N = 768; }
        else if (i < TE5) { j = i - TE4; W = Wa2; dst = g_wt + OFF_WA2T; K = 768; N = 768; }
        else if (i < TE6) { masks[i - TE5] = 1.0f; return; }
        else return;
        int k = j / N, n = j % N;
        dst[(size_t)n * K + k] = __float2half_rn(W[j]);
        return;
    }

    // ---------------- kNN (1024 threads, 8 pts/thread) ----------------
    {
        extern __shared__ unsigned long long keys[];   // PP entries
        __shared__ unsigned long long red2[32];
        __shared__ unsigned long long win_s;
        int lin = bid - BB - NT_BLK;
        int m = lin >> 4;          // slow: early blocks need early centroids
        int b = lin & 15;

        if (tid == 0) {
            while (((volatile int*)g_prog)[b] <= m) __nanosleep(100);
            __threadfence();       // acquire
        }
        __syncthreads();

        const float* c = g_cent + ((size_t)b * MM + m) * 4;
        float c0 = __ldcg(c + 0), c1 = __ldcg(c + 1), c2 = __ldcg(c + 2), c3 = __ldcg(c + 3);
        float cen2 = __fadd_rn(__fadd_rn(__fadd_rn(__fmul_rn(c0,c0), __fmul_rn(c1,c1)),
                                         __fmul_rn(c2,c2)), __fmul_rn(c3,c3));
        unsigned long long mymin = ~0ull;
#pragma unroll
        for (int it = 0; it < PP / 1024; it++) {
            int p = tid + it * 1024;
            const float* q = coords + ((size_t)b * PP + p) * 5;
            float x0 = q[1], x1 = q[2], x2 = q[3], x3 = q[4];
            float pts2 = __fadd_rn(__fadd_rn(__fadd_rn(__fmul_rn(x0,x0), __fmul_rn(x1,x1)),
                                             __fmul_rn(x2,x2)), __fmul_rn(x3,x3));
            float dot  = __fadd_rn(__fadd_rn(__fadd_rn(__fmul_rn(c0,x0), __fmul_rn(c1,x1)),
                                             __fmul_rn(c2,x2)), __fmul_rn(c3,x3));
            float d2 = __fsub_rn(__fadd_rn(cen2, pts2), __fmul_rn(2.0f, dot));
            unsigned u = __float_as_uint(d2);
            u = (u & 0x80000000u) ? ~u : (u | 0x80000000u);   // order-preserving map
            unsigned long long key = ((unsigned long long)u << 32) | (unsigned)p;
            keys[p] = key;
            if (key < mymin) mymin = key;
        }
        __syncthreads();

        int* outp = g_knn + ((size_t)b * MM + m) * KNN;
        for (int k = 0; k < KNN; k++) {
            unsigned long long v = mymin;
            for (int off = 16; off; off >>= 1) {
                unsigned long long o = __shfl_down_sync(0xFFFFFFFFu, v, off);
                if (o < v) v = o;
            }
            if ((tid & 31) == 0) red2[tid >> 5] = v;
            __syncthreads();
            if (tid < 32) {
                unsigned long long w = red2[tid];
                for (int off = 16; off; off >>= 1) {
                    unsigned long long o = __shfl_down_sync(0xFFFFFFFFu, w, off);
                    if (o < w) w = o;
                }
                if (tid == 0) {
                    win_s = w;
                    outp[k] = (int)(w & 0xFFFFFFFFu);
                }
            }
            __syncthreads();
            if (mymin == win_s) {
                keys[(unsigned)(mymin & 0xFFFFFFFFu)] = ~0ull;
                unsigned long long nm = ~0ull;
#pragma unroll
                for (int it = 0; it < PP / 1024; it++) {
                    unsigned long long t = keys[tid + it * 1024];
                    if (t < nm) nm = t;
                }
                mymin = nm;
            }
        }
    }
}

// ---------------- gather + layer1 (6 -> 256, relu): 8 rows per block, fp16 out ----
__global__ __launch_bounds__(256) void gather_mlp1(const float* __restrict__ feats,
                                                   const float* __restrict__ W1,
                                                   const float* __restrict__ b1)
{
    int j = threadIdx.x;
    int rowbase = blockIdx.x * 8;
    float w[6];
#pragma unroll
    for (int t = 0; t < 6; t++) w[t] = W1[t * 256 + j];
    float bb = b1[j];
    __shared__ float fs[8][6];
    if (j < 48) {
        int r = j / 6, cidx = j % 6;
        int row = rowbase + r;
        int bidx = row >> 11;                       // row / (MM*KNN)
        int idx = g_knn[row];
        fs[r][cidx] = feats[((size_t)bidx * PP + idx) * 6 + cidx];
    }
    __syncthreads();
#pragma unroll
    for (int r = 0; r < 8; r++) {
        float acc = bb;
#pragma unroll
        for (int t = 0; t < 6; t++) acc = fmaf(fs[r][t], w[t], acc);
        g_bufA[(size_t)(rowbase + r) * 256 + j] = __float2half_rn(fmaxf(acc, 0.f));
    }
}

// ================= fp16 mma.sync m16n8k16 GEMM, 4 warps / 64x64 warp tiles =========
// C[Mr,N] = act(A[Mr,K] @ Bt[N,K]^T + bias)    (A, Bt fp16; accumulate fp32)
// CTA tile 128x128, K chunks of 64 halves, 3-stage cp.async.
// 4 warps in 2(m) x 2(n); warp tile 64x64 -> 4 mt x 8 nt fragments, acc = 128 regs.
// Fragment smem traffic per chunk: 2xA + 2xB = 64KB (33% less than 4x2 grid).
#define SPAD 36                      // smem row stride in 32-bit words (=72 halves)
#define STG_MAT (128 * SPAD * 4)     // 18432 B per matrix per stage
#define STG_BYTES (2 * STG_MAT)      // 36864 B per stage (A + B)
#define NSTAGE 3
#define GSMEM (NSTAGE * STG_BYTES)   // 110592 B

__device__ __forceinline__ void cp16(uint32_t saddr, const void* g) {
    asm volatile("cp.async.cg.shared.global [%0], [%1], 16;" :: "r"(saddr), "l"(g));
}
__device__ __forceinline__ void ldmx4(uint32_t& r0, uint32_t& r1, uint32_t& r2, uint32_t& r3,
                                      uint32_t saddr) {
    asm volatile("ldmatrix.sync.aligned.m8n8.x4.shared.b16 {%0,%1,%2,%3}, [%4];"
                 : "=r"(r0), "=r"(r1), "=r"(r2), "=r"(r3) : "r"(saddr));
}

template<bool RELU, bool POOL, bool HALF_OUT>
__global__ __launch_bounds__(128, 2) void mma_gemm(
    const __half* __restrict__ A, const __half* __restrict__ Bt,
    const float* __restrict__ bias, void* __restrict__ Cv,
    int N, int K)
{
    extern __shared__ char dsm[];
    uint32_t sbase = (uint32_t)__cvta_generic_to_shared(dsm);
    int tid = threadIdx.x, wid = tid >> 5, lane = tid & 31;
    int gid = lane >> 2, tig = lane & 3;
    int bx = blockIdx.x, by = blockIdx.y;
    int m_base = (wid & 1) * 64;
    int n_base = (wid >> 1) * 64;

    const __half* Ag = A  + (size_t)(by * 128) * K;
    const __half* Bg = Bt + (size_t)(bx * 128) * K;

    // staging: 1024 16B-units per matrix per chunk; 128 threads -> 8 units each
    int srow[8], sq[8];
#pragma unroll
    for (int r = 0; r < 8; r++) {
        int id = tid + 128 * r;
        srow[r] = id >> 3;          // 0..127
        sq[r]   = id & 7;           // 16B unit within row
    }

    // ldmatrix per-thread word offsets
    int lr = lane & 7, mi = lane >> 3;
    int a_off[4], b_off[4];
#pragma unroll
    for (int mt = 0; mt < 4; mt++)
        a_off[mt] = (m_base + mt * 16 + lr + (mi & 1) * 8) * SPAD + (mi >> 1) * 4;
#pragma unroll
    for (int nt2 = 0; nt2 < 4; nt2++)
        b_off[nt2] = (n_base + nt2 * 16 + lr + (mi >> 1) * 8) * SPAD + (mi & 1) * 4;

    float acc[4][8][4];
#pragma unroll
    for (int mt = 0; mt < 4; mt++)
#pragma unroll
        for (int nt = 0; nt < 8; nt++)
#pragma unroll
            for (int j = 0; j < 4; j++) acc[mt][nt][j] = 0.f;

    int NC = K >> 6;   // chunks of 64 halves

#pragma unroll
    for (int s = 0; s < 2; s++) {
        int kb = s << 6;
        uint32_t stb = sbase + s * STG_BYTES;
#pragma unroll
        for (int r = 0; r < 8; r++) {
            uint32_t doff = (uint32_t)(srow[r] * (SPAD * 4) + sq[r] * 16);
            cp16(stb + doff,           Ag + (size_t)srow[r] * K + kb + sq[r] * 8);
            cp16(stb + STG_MAT + doff, Bg + (size_t)srow[r] * K + kb + sq[r] * 8);
        }
        asm volatile("cp.async.commit_group;" ::: "memory");
    }

    for (int c = 0; c < NC; c++) {
        asm volatile("cp.async.wait_group 1;" ::: "memory");
        __syncthreads();

        if (c + 2 < NC) {
            int kb = (c + 2) << 6;
            uint32_t stb = sbase + ((c + 2) % NSTAGE) * STG_BYTES;
#pragma unroll
            for (int r = 0; r < 8; r++) {
                uint32_t doff = (uint32_t)(srow[r] * (SPAD * 4) + sq[r] * 16);
                cp16(stb + doff,           Ag + (size_t)srow[r] * K + kb + sq[r] * 8);
                cp16(stb + STG_MAT + doff, Bg + (size_t)srow[r] * K + kb + sq[r] * 8);
            }
        }
        asm volatile("cp.async.commit_group;" ::: "memory");

        uint32_t aBase = sbase + (c % NSTAGE) * STG_BYTES;
        uint32_t bBase = aBase + STG_MAT;

#pragma unroll
        for (int ks = 0; ks < 4; ks++) {
            int k0 = ks * 8;
            uint32_t af[4][4];
#pragma unroll
            for (int mt = 0; mt < 4; mt++)
                ldmx4(af[mt][0], af[mt][1], af[mt][2], af[mt][3],
                      aBase + (uint32_t)(a_off[mt] + k0) * 4);
#pragma unroll
            for (int nt2 = 0; nt2 < 4; nt2++) {
                uint32_t bf0, bf1, bf2, bf3;
                ldmx4(bf0, bf1, bf2, bf3, bBase + (uint32_t)(b_off[nt2] + k0) * 4);
#pragma unroll
                for (int mt = 0; mt < 4; mt++) {
                    asm volatile(
                        "mma.sync.aligned.m16n8k16.row.col.f32.f16.f16.f32 "
                        "{%0,%1,%2,%3}, {%4,%5,%6,%7}, {%8,%9}, {%0,%1,%2,%3};"
                        : "+f"(acc[mt][nt2*2][0]), "+f"(acc[mt][nt2*2][1]),
                          "+f"(acc[mt][nt2*2][2]), "+f"(acc[mt][nt2*2][3])
                        : "r"(af[mt][0]), "r"(af[mt][1]), "r"(af[mt][2]), "r"(af[mt][3]),
                          "r"(bf0), "r"(bf1));
                }
#pragma unroll
                for (int mt = 0; mt < 4; mt++) {
                    asm volatile(
                        "mma.sync.aligned.m16n8k16.row.col.f32.f16.f16.f32 "
                        "{%0,%1,%2,%3}, {%4,%5,%6,%7}, {%8,%9}, {%0,%1,%2,%3};"
                        : "+f"(acc[mt][nt2*2+1][0]), "+f"(acc[mt][nt2*2+1][1]),
                          "+f"(acc[mt][nt2*2+1][2]), "+f"(acc[mt][nt2*2+1][3])
                        : "r"(af[mt][0]), "r"(af[mt][1]), "r"(af[mt][2]), "r"(af[mt][3]),
                          "r"(bf2), "r"(bf3));
                }
            }
        }
    }

    // ---- epilogue (fragment ownership convention unchanged) ----
#pragma unroll
    for (int nt = 0; nt < 8; nt++) {
        int cg = bx * 128 + n_base + nt * 8 + 2 * tig;
        float bz0 = bias[cg], bz1 = bias[cg + 1];
#pragma unroll
        for (int mt = 0; mt < 4; mt++) {
            float v0 = acc[mt][nt][0] + bz0;
            float v1 = acc[mt][nt][1] + bz1;
            float v2 = acc[mt][nt][2] + bz0;
            float v3 = acc[mt][nt][3] + bz1;
            if (RELU) {
                v0 = fmaxf(v0, 0.f); v1 = fmaxf(v1, 0.f);
                v2 = fmaxf(v2, 0.f); v3 = fmaxf(v3, 0.f);
            }
            if (POOL) {
                float m0 = fmaxf(v0, v2);
                float m1 = fmaxf(v1, v3);
#pragma unroll
                for (int off = 4; off <= 16; off <<= 1) {
                    m0 = fmaxf(m0, __shfl_xor_sync(0xFFFFFFFFu, m0, off));
                    m1 = fmaxf(m1, __shfl_xor_sync(0xFFFFFFFFu, m1, off));
                }
                if (gid == 0) {
                    int q = (by * 128 + m_base + mt * 16) >> 4;
                    __half* C = (__half*)Cv;
                    *(__half2*)(C + (size_t)q * N + cg) = __floats2half2_rn(m0, m1);
                }
            } else if (HALF_OUT) {
                int rg = by * 128 + m_base + mt * 16 + gid;
                __half* C = (__half*)Cv;
                *(__half2*)(C + (size_t)rg * N + cg)       = __floats2half2_rn(v0, v1);
                *(__half2*)(C + (size_t)(rg + 8) * N + cg) = __floats2half2_rn(v2, v3);
            } else {
                int rg = by * 128 + m_base + mt * 16 + gid;
                float* C = (float*)Cv;
                *(float2*)(C + (size_t)rg * N + cg)       = make_float2(v0, v1);
                *(float2*)(C + (size_t)(rg + 8) * N + cg) = make_float2(v2, v3);
            }
        }
    }
}

// ---------------- launcher ---------------------------------------------------------
extern "C" void kernel_launch(void* const* d_in, const int* in_sizes, int n_in,
                              void* d_out, int out_size)
{
    const float* coords = (const float*)d_in[0];
    const float* feats  = (const float*)d_in[1];
    const float* W1 = (const float*)d_in[2];  const float* b1 = (const float*)d_in[3];
    const float* W2 = (const float*)d_in[4];  const float* b2 = (const float*)d_in[5];
    const float* W3 = (const float*)d_in[6];  const float* b3 = (const float*)d_in[7];
    const float* W4 = (const float*)d_in[8];  const float* b4 = (const float*)d_in[9];
    const float* Wa1 = (const float*)d_in[10]; const float* ba1 = (const float*)d_in[11];
    const float* Wa2 = (const float*)d_in[12]; const float* ba2 = (const float*)d_in[13];

    float* out     = (float*)d_out;
    float* tokens  = out;                               // [QQ, DD]
    float* centout = out + (size_t)QQ * DD;             // [QQ, 4]
    float* masks   = centout + (size_t)QQ * 4;          // [QQ]

    __half *pA, *pB, *pPool, *pH, *pWt;
    cudaGetSymbolAddress((void**)&pA, g_bufA);
    cudaGetSymbolAddress((void**)&pB, g_bufB);
    cudaGetSymbolAddress((void**)&pPool, g_pool);
    cudaGetSymbolAddress((void**)&pH, g_h);
    cudaGetSymbolAddress((void**)&pWt, g_wt);

    // 1. reset centroid-progress flags (must precede fused kernel every replay)
    reset_prog<<<1, 32>>>();

    // 2. fused FPS + transpose/mask + kNN (kNN overlaps FPS via progress flags)
    cudaFuncSetAttribute(fused_front, cudaFuncAttributeMaxDynamicSharedMemorySize, PP * 8);
    fused_front<<<FUSED_GRID, 1024, PP * 8>>>(coords, centout,
                                              W2, W3, W4, Wa1, Wa2, masks);

    // 3. gather + layer1 (6 -> 256, relu, fp16 out) -> g_bufA
    gather_mlp1<<<RR / 8, 256>>>(feats, W1, b1);

    // 4. MLP chain on fp16 tensor cores (128-thread CTAs, 64x64 warp tiles)
    cudaFuncSetAttribute((const void*)mma_gemm<true,  false, true >, cudaFuncAttributeMaxDynamicSharedMemorySize, GSMEM);
    cudaFuncSetAttribute((const void*)mma_gemm<false, true,  true >, cudaFuncAttributeMaxDynamicSharedMemorySize, GSMEM);
    cudaFuncSetAttribute((const void*)mma_gemm<false, false, false>, cudaFuncAttributeMaxDynamicSharedMemorySize, GSMEM);
    mma_gemm<true,  false, true ><<<dim3(512 / 128, RR / 128), 128, GSMEM>>>(pA, pWt + OFF_W2T, b2, pB, 512, 256);
    mma_gemm<true,  false, true ><<<dim3(768 / 128, RR / 128), 128, GSMEM>>>(pB, pWt + OFF_W3T, b3, pA, 768, 512);
    // layer 4: output pooled directly into g_pool [QQ, 768] (fp16)
    mma_gemm<false, true,  true ><<<dim3(768 / 128, RR / 128), 128, GSMEM>>>(pA, pWt + OFF_W4T, b4, pPool, 768, 768);

    // 5. attention MLP -> tokens (final layer fp32 out)
    mma_gemm<true,  false, true ><<<dim3(DD / 128, QQ / 128), 128, GSMEM>>>(pPool, pWt + OFF_WA1T, ba1, pH, 768, 768);
    mma_gemm<false, false, false><<<dim3(DD / 128, QQ / 128), 128, GSMEM>>>(pH, pWt + OFF_WA2T, ba2, tokens, 768, 768);
}